// round 9
// baseline (speedup 1.0000x reference)
#include <cuda_runtime.h>
#include <cuda_bf16.h>

#define PDIM 1024
#define MDIM 64
#define RDIM 32
#define TI   4        // rows per block
#define NTH  512      // threads per block (128 per row)

__global__ __launch_bounds__(NTH, 2) void social_fused(
    const float* __restrict__ h,
    const float* __restrict__ corr,
    const int*   __restrict__ nei,
    const float* __restrict__ W_rela,
    const float* __restrict__ b_rela,
    const float* __restrict__ W_att,
    const float* __restrict__ b_att,
    float*       __restrict__ out)
{
    __shared__ float sW0[RDIM], sW1[RDIM], sbr[RDIM], swr[RDIM];
    __shared__ float snei[PDIM];
    __shared__ float shi[TI];
    __shared__ float swj[PDIM * TI];     // weights, j-major: [j][li]
    __shared__ float sredA[16];
    __shared__ float sredB[16];
    __shared__ float spart[8 * 256];     // [g][row][m]

    const int tid = threadIdx.x;
    const int li  = tid >> 7;            // row within tile, 0..3
    const int lt  = tid & 127;           // lane within row, 0..127
    const int w   = tid >> 5;            // warp id, 0..15
    const int l   = tid & 31;            // lane
    const int iglob = blockIdx.x * TI + li;

    if (tid < RDIM) {
        sW0[tid] = W_rela[tid];
        sW1[tid] = W_rela[RDIM + tid];
        sbr[tid] = b_rela[tid];
        swr[tid] = W_att[tid];
    }

    // ---- fused prolog A: snei[j] = h[j]·w_nei, 64 rows per warp, coalesced ----
    {
        const float wn0 = W_att[RDIM + MDIM + l];
        const float wn1 = W_att[RDIM + MDIM + l + 32];
        const float* hb = h + (size_t)(w * 64) * MDIM;
#pragma unroll 4
        for (int it = 0; it < 32; it++) {
            const float* h0 = hb + (size_t)(2 * it) * MDIM;
            float a0 = fmaf(h0[l],          wn0, h0[l + 32] * wn1);
            float a1 = fmaf(h0[MDIM + l],   wn0, h0[MDIM + l + 32] * wn1);
#pragma unroll
            for (int o = 16; o > 0; o >>= 1) {
                a0 += __shfl_xor_sync(0xffffffffu, a0, o);
                a1 += __shfl_xor_sync(0xffffffffu, a1, o);
            }
            if (l == 0) {
                snei[w * 64 + 2 * it]     = a0;
                snei[w * 64 + 2 * it + 1] = a1;
            }
        }
    }
    // ---- fused prolog B: bias for this block's 4 rows (warps 0..3) ----
    if (w < TI) {
        const float wh0 = W_att[RDIM + l];
        const float wh1 = W_att[RDIM + l + 32];
        const float* h0 = h + (size_t)(blockIdx.x * TI + w) * MDIM;
        float a = fmaf(h0[l], wh0, h0[l + 32] * wh1);
#pragma unroll
        for (int o = 16; o > 0; o >>= 1)
            a += __shfl_xor_sync(0xffffffffu, a, o);
        if (l == 0) shi[w] = a + b_att[0];
    }
    __syncthreads();

    const float bias = shi[li];
    const int jbase = lt * 8;            // 8 contiguous j's per thread

    // ---- pass 1: load corr (float4) + nei (int4) for 8 j's ----
    const float4* crow4 = reinterpret_cast<const float4*>(corr + (size_t)iglob * PDIM * 2) + lt * 4;
    const int4*   nrow4 = reinterpret_cast<const int4*>(nei + (size_t)iglob * PDIM) + lt * 2;

    float4 cv[4];
    int4   nv[2];
#pragma unroll
    for (int t = 0; t < 4; t++) cv[t] = crow4[t];
#pragma unroll
    for (int t = 0; t < 2; t++) nv[t] = nrow4[t];

    float cx[8], cy[8];
#pragma unroll
    for (int t = 0; t < 4; t++) {
        cx[2*t]   = cv[t].x;  cy[2*t]   = cv[t].y;
        cx[2*t+1] = cv[t].z;  cy[2*t+1] = cv[t].w;
    }
    unsigned mbits = 0;
    {
        const int* ni = reinterpret_cast<const int*>(nv);
#pragma unroll
        for (int k = 0; k < 8; k++) if (ni[k] > 0) mbits |= 1u << k;
    }

    float s[8];
#pragma unroll
    for (int k = 0; k < 8; k++) s[k] = 0.f;

#pragma unroll
    for (int r = 0; r < RDIM; r++) {
        const float A = sW0[r], B = sW1[r], Cb = sbr[r], Wr = swr[r];
#pragma unroll
        for (int k = 0; k < 8; k++) {
            float re = fmaf(cx[k], A, fmaf(cy[k], B, Cb));
            re = fmaxf(re, 0.f);
            s[k] = fmaf(re, Wr, s[k]);
        }
    }

    float lmax = -1e30f;
#pragma unroll
    for (int k = 0; k < 8; k++) {
        float v = s[k] + bias + snei[jbase + k];
        v = (mbits >> k & 1u) ? v : 0.f;     // masked -> 0
        if (v == 0.f) v = -1e-6f;            // exact reference semantics
        s[k] = v;
        lmax = fmaxf(lmax, v);
    }

    // ---- row softmax: 128 threads = 4 warps per row ----
#pragma unroll
    for (int o = 16; o > 0; o >>= 1)
        lmax = fmaxf(lmax, __shfl_xor_sync(0xffffffffu, lmax, o));
    if (l == 0) sredA[w] = lmax;             // w = li*4 + warp-in-row
    __syncthreads();
    const float rmax = fmaxf(fmaxf(sredA[li*4+0], sredA[li*4+1]),
                             fmaxf(sredA[li*4+2], sredA[li*4+3]));

    float lsum = 0.f;
#pragma unroll
    for (int k = 0; k < 8; k++) {
        float e = __expf(s[k] - rmax);
        s[k] = e;
        lsum += e;
    }
#pragma unroll
    for (int o = 16; o > 0; o >>= 1)
        lsum += __shfl_xor_sync(0xffffffffu, lsum, o);
    if (l == 0) sredB[w] = lsum;
    __syncthreads();
    const float inv = 1.0f / (sredB[li*4+0] + sredB[li*4+1] +
                              sredB[li*4+2] + sredB[li*4+3]);

#pragma unroll
    for (int k = 0; k < 8; k++) {
        swj[(jbase + k) * TI + li] = (mbits >> k & 1u) ? s[k] * inv : 0.f;
    }
    __syncthreads();

    // ---- pass 2: out[row][m] = sum_j w[row][j] * h[j][m], 8-way j split ----
    const int m = tid & 63;
    const int g = tid >> 6;                  // j-chunk, 0..7 (128 j's each)
    float a0 = 0.f, a1 = 0.f, a2 = 0.f, a3 = 0.f;
    const float4* wv = reinterpret_cast<const float4*>(swj) + g * 128;
    const float*  hp = h + (size_t)(g * 128) * MDIM + m;
#pragma unroll 4
    for (int jj = 0; jj < 128; jj++) {
        float4 w4 = wv[jj];                  // broadcast LDS.128: 4 rows' weights
        float  hv = hp[(size_t)jj * MDIM];   // coalesced across m
        a0 = fmaf(w4.x, hv, a0);
        a1 = fmaf(w4.y, hv, a1);
        a2 = fmaf(w4.z, hv, a2);
        a3 = fmaf(w4.w, hv, a3);
    }
    spart[g * 256 + 0 * 64 + m] = a0;
    spart[g * 256 + 1 * 64 + m] = a1;
    spart[g * 256 + 2 * 64 + m] = a2;
    spart[g * 256 + 3 * 64 + m] = a3;
    __syncthreads();

    if (tid < 256) {
        float o = 0.f;
#pragma unroll
        for (int gg = 0; gg < 8; gg++) o += spart[gg * 256 + tid];
        out[(size_t)blockIdx.x * TI * MDIM + tid] = o;
    }
}

extern "C" void kernel_launch(void* const* d_in, const int* in_sizes, int n_in,
                              void* d_out, int out_size) {
    const float* h      = (const float*)d_in[0];
    const float* corr   = (const float*)d_in[1];
    const int*   nei    = (const int*)d_in[2];
    const float* W_rela = (const float*)d_in[3];
    const float* b_rela = (const float*)d_in[4];
    const float* W_att  = (const float*)d_in[5];
    const float* b_att  = (const float*)d_in[6];
    float* out = (float*)d_out;

    social_fused<<<PDIM / TI, NTH>>>(h, corr, nei, W_rela, b_rela, W_att, b_att, out);
}

// round 10
// speedup vs baseline: 1.4369x; 1.4369x over previous
#include <cuda_runtime.h>
#include <cuda_bf16.h>

#define PDIM 1024
#define MDIM 64
#define RDIM 32
#define TI   4        // rows per block
#define NTH  512      // threads per block (128 per row)

__device__ float d_hi[PDIM];
__device__ float d_nei[PDIM];

// Prolog: one warp per output value. 2048 warps total.
//   gid < 1024  : d_hi[row]  = h[row]·w_hi
//   gid >= 1024 : d_nei[row] = h[row]·w_nei
__global__ __launch_bounds__(512) void prep_kernel(const float* __restrict__ h,
                                                   const float* __restrict__ W_att) {
    const int l   = threadIdx.x & 31;
    const int gid = blockIdx.x * 16 + (threadIdx.x >> 5);   // global warp id, 0..2047
    const int row = gid & (PDIM - 1);
    const int sel = gid >> 10;                              // 0 = hi, 1 = nei
    const float* w  = W_att + RDIM + sel * MDIM;
    const float* hr = h + (size_t)row * MDIM;
    float a = fmaf(hr[l], w[l], hr[l + 32] * w[l + 32]);
#pragma unroll
    for (int o = 16; o > 0; o >>= 1)
        a += __shfl_xor_sync(0xffffffffu, a, o);
    if (l == 0) {
        if (sel == 0) d_hi[row] = a;
        else          d_nei[row] = a;
    }
}

__global__ __launch_bounds__(NTH, 2) void social_kernel(
    const float* __restrict__ h,
    const float* __restrict__ corr,
    const int*   __restrict__ nei,
    const float* __restrict__ W_rela,
    const float* __restrict__ b_rela,
    const float* __restrict__ W_att,
    const float* __restrict__ b_att,
    float*       __restrict__ out)
{
    __shared__ float sW0[RDIM], sW1[RDIM], sbr[RDIM], swr[RDIM];
    __shared__ float snei[PDIM];
    __shared__ float swj[PDIM * TI];     // weights, j-major: [j][li]
    __shared__ float sredA[16];
    __shared__ float sredB[16];
    __shared__ float spart[8 * 256];     // [g][row][m]

    const int tid = threadIdx.x;
    const int li  = tid >> 7;            // row within tile, 0..3
    const int lt  = tid & 127;           // lane within row, 0..127
    const int iglob = blockIdx.x * TI + li;

    if (tid < RDIM) {
        sW0[tid] = W_rela[tid];
        sW1[tid] = W_rela[RDIM + tid];
        sbr[tid] = b_rela[tid];
        swr[tid] = W_att[tid];
    }
    for (int j = tid; j < PDIM; j += NTH) snei[j] = d_nei[j];
    __syncthreads();

    const float bias = d_hi[iglob] + b_att[0];
    const int jbase = lt * 8;            // 8 contiguous j's per thread

    // ---- pass 1: load corr (float4) + nei (int4) for 8 j's ----
    const float4* crow4 = reinterpret_cast<const float4*>(corr + (size_t)iglob * PDIM * 2) + lt * 4;
    const int4*   nrow4 = reinterpret_cast<const int4*>(nei + (size_t)iglob * PDIM) + lt * 2;

    float4 cv[4];
    int4   nv[2];
#pragma unroll
    for (int t = 0; t < 4; t++) cv[t] = crow4[t];
#pragma unroll
    for (int t = 0; t < 2; t++) nv[t] = nrow4[t];

    float cx[8], cy[8];
#pragma unroll
    for (int t = 0; t < 4; t++) {
        cx[2*t]   = cv[t].x;  cy[2*t]   = cv[t].y;
        cx[2*t+1] = cv[t].z;  cy[2*t+1] = cv[t].w;
    }
    unsigned mbits = 0;
    {
        const int* ni = reinterpret_cast<const int*>(nv);
#pragma unroll
        for (int k = 0; k < 8; k++) if (ni[k] > 0) mbits |= 1u << k;
    }

    float s[8];
#pragma unroll
    for (int k = 0; k < 8; k++) s[k] = 0.f;

#pragma unroll
    for (int r = 0; r < RDIM; r++) {
        const float A = sW0[r], B = sW1[r], Cb = sbr[r], Wr = swr[r];
#pragma unroll
        for (int k = 0; k < 8; k++) {
            float re = fmaf(cx[k], A, fmaf(cy[k], B, Cb));
            re = fmaxf(re, 0.f);
            s[k] = fmaf(re, Wr, s[k]);
        }
    }

    float lmax = -1e30f;
#pragma unroll
    for (int k = 0; k < 8; k++) {
        float v = s[k] + bias + snei[jbase + k];
        v = (mbits >> k & 1u) ? v : 0.f;     // masked -> 0
        if (v == 0.f) v = -1e-6f;            // exact reference semantics
        s[k] = v;
        lmax = fmaxf(lmax, v);
    }

    // ---- row softmax: 128 threads = 4 warps per row ----
#pragma unroll
    for (int o = 16; o > 0; o >>= 1)
        lmax = fmaxf(lmax, __shfl_xor_sync(0xffffffffu, lmax, o));
    if ((tid & 31) == 0) sredA[tid >> 5] = lmax;   // [li*4 + warp-in-row]
    __syncthreads();
    const float rmax = fmaxf(fmaxf(sredA[li*4+0], sredA[li*4+1]),
                             fmaxf(sredA[li*4+2], sredA[li*4+3]));

    float lsum = 0.f;
#pragma unroll
    for (int k = 0; k < 8; k++) {
        float e = __expf(s[k] - rmax);
        s[k] = e;
        lsum += e;
    }
#pragma unroll
    for (int o = 16; o > 0; o >>= 1)
        lsum += __shfl_xor_sync(0xffffffffu, lsum, o);
    if ((tid & 31) == 0) sredB[tid >> 5] = lsum;
    __syncthreads();
    const float inv = 1.0f / (sredB[li*4+0] + sredB[li*4+1] +
                              sredB[li*4+2] + sredB[li*4+3]);

#pragma unroll
    for (int k = 0; k < 8; k++) {
        swj[(jbase + k) * TI + li] = (mbits >> k & 1u) ? s[k] * inv : 0.f;
    }
    __syncthreads();

    // ---- pass 2: out[row][m] = sum_j w[row][j] * h[j][m], 8-way j split ----
    const int m = tid & 63;
    const int g = tid >> 6;                  // j-chunk, 0..7 (128 j's each)
    float a0 = 0.f, a1 = 0.f, a2 = 0.f, a3 = 0.f;
    const float4* wv = reinterpret_cast<const float4*>(swj) + g * 128;
    const float*  hp = h + (size_t)(g * 128) * MDIM + m;
#pragma unroll 4
    for (int jj = 0; jj < 128; jj++) {
        float4 w4 = wv[jj];                  // broadcast LDS.128: 4 rows' weights
        float  hv = hp[(size_t)jj * MDIM];   // coalesced across m
        a0 = fmaf(w4.x, hv, a0);
        a1 = fmaf(w4.y, hv, a1);
        a2 = fmaf(w4.z, hv, a2);
        a3 = fmaf(w4.w, hv, a3);
    }
    spart[g * 256 + 0 * 64 + m] = a0;
    spart[g * 256 + 1 * 64 + m] = a1;
    spart[g * 256 + 2 * 64 + m] = a2;
    spart[g * 256 + 3 * 64 + m] = a3;
    __syncthreads();

    if (tid < 256) {
        float o = 0.f;
#pragma unroll
        for (int gg = 0; gg < 8; gg++) o += spart[gg * 256 + tid];
        out[(size_t)blockIdx.x * TI * MDIM + tid] = o;
    }
}

extern "C" void kernel_launch(void* const* d_in, const int* in_sizes, int n_in,
                              void* d_out, int out_size) {
    const float* h      = (const float*)d_in[0];
    const float* corr   = (const float*)d_in[1];
    const int*   nei    = (const int*)d_in[2];
    const float* W_rela = (const float*)d_in[3];
    const float* b_rela = (const float*)d_in[4];
    const float* W_att  = (const float*)d_in[5];
    const float* b_att  = (const float*)d_in[6];
    float* out = (float*)d_out;

    prep_kernel<<<128, 512>>>(h, W_att);
    social_kernel<<<PDIM / TI, NTH>>>(h, corr, nei, W_rela, b_rela, W_att, b_att, out);
}

// round 11
// speedup vs baseline: 1.7374x; 1.2092x over previous
#include <cuda_runtime.h>
#include <cuda_bf16.h>

#define PDIM 1024
#define MDIM 64
#define RDIM 32
#define TI   4        // rows per block
#define NTH  512      // threads per block (128 per row)

typedef unsigned long long ull;

#define FMA2(d, a, b, c) \
    asm("fma.rn.f32x2 %0, %1, %2, %3;" : "=l"(d) : "l"(a), "l"(b), "l"(c))
#define PACKF2(d, lo, hi) \
    asm("mov.b64 %0, {%1, %2};" : "=l"(d) : "r"(__float_as_uint(lo)), "r"(__float_as_uint(hi)))
#define UNPACKF2(lo, hi, d) do { unsigned _ul, _uh; \
    asm("mov.b64 {%0, %1}, %2;" : "=r"(_ul), "=r"(_uh) : "l"(d)); \
    lo = __uint_as_float(_ul); hi = __uint_as_float(_uh); } while (0)

__device__ float d_hi[PDIM];
__device__ float d_nei[PDIM];

// Prolog: one warp per output value. 2048 warps total.
__global__ __launch_bounds__(512) void prep_kernel(const float* __restrict__ h,
                                                   const float* __restrict__ W_att) {
    const int l   = threadIdx.x & 31;
    const int gid = blockIdx.x * 16 + (threadIdx.x >> 5);   // 0..2047
    const int row = gid & (PDIM - 1);
    const int sel = gid >> 10;                              // 0 = hi, 1 = nei
    const float* w  = W_att + RDIM + sel * MDIM;
    const float* hr = h + (size_t)row * MDIM;
    float a = fmaf(hr[l], w[l], hr[l + 32] * w[l + 32]);
#pragma unroll
    for (int o = 16; o > 0; o >>= 1)
        a += __shfl_xor_sync(0xffffffffu, a, o);
    if (l == 0) {
        if (sel == 0) d_hi[row] = a;
        else          d_nei[row] = a;
    }
}

__global__ __launch_bounds__(NTH, 2) void social_kernel(
    const float* __restrict__ h,
    const float* __restrict__ corr,
    const int*   __restrict__ nei,
    const float* __restrict__ W_rela,
    const float* __restrict__ b_rela,
    const float* __restrict__ W_att,
    const float* __restrict__ b_att,
    float*       __restrict__ out)
{
    __shared__ ull   sW0d[RDIM], sW1d[RDIM], sbrd[RDIM], swrd[RDIM]; // duplicated pairs
    __shared__ float snei[PDIM];
    __shared__ float swjT[TI * PDIM];     // weights, row-major: [li][j]
    __shared__ float sredA[16];
    __shared__ float sredB[16];
    __shared__ float2 spart2[16 * TI * 32];  // [g][row][m2]

    const int tid = threadIdx.x;
    const int li  = tid >> 7;            // row within tile, 0..3
    const int lt  = tid & 127;           // lane within row, 0..127
    const int iglob = blockIdx.x * TI + li;

    if (tid < RDIM) {
        float a = W_rela[tid];          PACKF2(sW0d[tid], a, a);
        float b = W_rela[RDIM + tid];   PACKF2(sW1d[tid], b, b);
        float c = b_rela[tid];          PACKF2(sbrd[tid], c, c);
        float d = W_att[tid];           PACKF2(swrd[tid], d, d);
    }
    for (int j = tid; j < PDIM; j += NTH) snei[j] = d_nei[j];
    __syncthreads();

    const float bias = d_hi[iglob] + b_att[0];
    const int jbase = lt * 8;            // 8 contiguous j's per thread

    // ---- pass 1: load corr (float4) + nei (int4) for 8 j's ----
    const float4* crow4 = reinterpret_cast<const float4*>(corr + (size_t)iglob * PDIM * 2) + lt * 4;
    const int4*   nrow4 = reinterpret_cast<const int4*>(nei + (size_t)iglob * PDIM) + lt * 2;

    float4 cv[4];
    int4   nv[2];
#pragma unroll
    for (int t = 0; t < 4; t++) cv[t] = crow4[t];
#pragma unroll
    for (int t = 0; t < 2; t++) nv[t] = nrow4[t];

    // pack (k=2t, k=2t+1) pairs: cv[t] = (x0,y0,x1,y1) for j = jbase+2t, +2t+1
    ull cxP[4], cyP[4];
#pragma unroll
    for (int t = 0; t < 4; t++) {
        PACKF2(cxP[t], cv[t].x, cv[t].z);
        PACKF2(cyP[t], cv[t].y, cv[t].w);
    }
    unsigned mbits = 0;
    {
        const int* ni = reinterpret_cast<const int*>(nv);
#pragma unroll
        for (int k = 0; k < 8; k++) if (ni[k] > 0) mbits |= 1u << k;
    }

    ull sP[4];
#pragma unroll
    for (int t = 0; t < 4; t++) sP[t] = 0ull;

#pragma unroll
    for (int r = 0; r < RDIM; r++) {
        const ull AA = sW0d[r], BB = sW1d[r], CC = sbrd[r], WW = swrd[r];
#pragma unroll
        for (int t = 0; t < 4; t++) {
            ull u;
            FMA2(u, cyP[t], BB, CC);
            FMA2(u, cxP[t], AA, u);
            float lo, hi;
            UNPACKF2(lo, hi, u);
            lo = fmaxf(lo, 0.f);
            hi = fmaxf(hi, 0.f);
            ull re;
            PACKF2(re, lo, hi);
            FMA2(sP[t], re, WW, sP[t]);
        }
    }

    float s[8];
#pragma unroll
    for (int t = 0; t < 4; t++) UNPACKF2(s[2*t], s[2*t+1], sP[t]);

    // snei for my 8 j's: two LDS.128
    float4 n4a = *reinterpret_cast<const float4*>(&snei[jbase]);
    float4 n4b = *reinterpret_cast<const float4*>(&snei[jbase + 4]);
    const float nadd[8] = {n4a.x, n4a.y, n4a.z, n4a.w, n4b.x, n4b.y, n4b.z, n4b.w};

    float lmax = -1e30f;
#pragma unroll
    for (int k = 0; k < 8; k++) {
        float v = s[k] + bias + nadd[k];
        v = (mbits >> k & 1u) ? v : 0.f;     // masked -> 0
        if (v == 0.f) v = -1e-6f;            // exact reference semantics
        s[k] = v;
        lmax = fmaxf(lmax, v);
    }

    // ---- row softmax: 128 threads = 4 warps per row ----
#pragma unroll
    for (int o = 16; o > 0; o >>= 1)
        lmax = fmaxf(lmax, __shfl_xor_sync(0xffffffffu, lmax, o));
    if ((tid & 31) == 0) sredA[tid >> 5] = lmax;   // [li*4 + warp-in-row]
    __syncthreads();
    const float rmax = fmaxf(fmaxf(sredA[li*4+0], sredA[li*4+1]),
                             fmaxf(sredA[li*4+2], sredA[li*4+3]));

    float lsum = 0.f;
#pragma unroll
    for (int k = 0; k < 8; k++) {
        float e = __expf(s[k] - rmax);
        s[k] = e;
        lsum += e;
    }
#pragma unroll
    for (int o = 16; o > 0; o >>= 1)
        lsum += __shfl_xor_sync(0xffffffffu, lsum, o);
    if ((tid & 31) == 0) sredB[tid >> 5] = lsum;
    __syncthreads();
    const float inv = 1.0f / (sredB[li*4+0] + sredB[li*4+1] +
                              sredB[li*4+2] + sredB[li*4+3]);

    // conflict-free weight store: 2x STS.128 per thread, row-major [li][j]
    {
        float w[8];
#pragma unroll
        for (int k = 0; k < 8; k++)
            w[k] = (mbits >> k & 1u) ? s[k] * inv : 0.f;
        float4* dst = reinterpret_cast<float4*>(&swjT[li * PDIM + jbase]);
        dst[0] = make_float4(w[0], w[1], w[2], w[3]);
        dst[1] = make_float4(w[4], w[5], w[6], w[7]);
    }
    __syncthreads();

    // ---- pass 2: out[row][m] = sum_j w[row][j] * h[j][m], 16-way j split, float2 m ----
    const int m2 = tid & 31;                 // m = 2*m2, 2*m2+1
    const int g  = tid >> 5;                 // j-chunk, 0..15 (64 j's each)
    const int jb = g * 64;
    float2 a0 = {0.f,0.f}, a1 = {0.f,0.f}, a2 = {0.f,0.f}, a3 = {0.f,0.f};
    const float2* hp = reinterpret_cast<const float2*>(h) + (size_t)jb * 32 + m2;

#pragma unroll 2
    for (int q4 = 0; q4 < 16; q4++) {
        // broadcast LDS.128: 4 j-weights per row
        float4 w0 = *reinterpret_cast<const float4*>(&swjT[0 * PDIM + jb + q4 * 4]);
        float4 w1 = *reinterpret_cast<const float4*>(&swjT[1 * PDIM + jb + q4 * 4]);
        float4 w2 = *reinterpret_cast<const float4*>(&swjT[2 * PDIM + jb + q4 * 4]);
        float4 w3 = *reinterpret_cast<const float4*>(&swjT[3 * PDIM + jb + q4 * 4]);
#define STEP(q, comp) { \
        float2 hv = hp[(size_t)(q4 * 4 + q) * 32]; \
        a0.x = fmaf(w0.comp, hv.x, a0.x); a0.y = fmaf(w0.comp, hv.y, a0.y); \
        a1.x = fmaf(w1.comp, hv.x, a1.x); a1.y = fmaf(w1.comp, hv.y, a1.y); \
        a2.x = fmaf(w2.comp, hv.x, a2.x); a2.y = fmaf(w2.comp, hv.y, a2.y); \
        a3.x = fmaf(w3.comp, hv.x, a3.x); a3.y = fmaf(w3.comp, hv.y, a3.y); }
        STEP(0, x) STEP(1, y) STEP(2, z) STEP(3, w)
#undef STEP
    }
    spart2[(g * TI + 0) * 32 + m2] = a0;
    spart2[(g * TI + 1) * 32 + m2] = a1;
    spart2[(g * TI + 2) * 32 + m2] = a2;
    spart2[(g * TI + 3) * 32 + m2] = a3;
    __syncthreads();

    if (tid < 256) {
        const float* sp = reinterpret_cast<const float*>(spart2);
        float o = 0.f;
#pragma unroll
        for (int gg = 0; gg < 16; gg++) o += sp[gg * 256 + tid];
        out[(size_t)blockIdx.x * TI * MDIM + tid] = o;
    }
}

extern "C" void kernel_launch(void* const* d_in, const int* in_sizes, int n_in,
                              void* d_out, int out_size) {
    const float* h      = (const float*)d_in[0];
    const float* corr   = (const float*)d_in[1];
    const int*   nei    = (const int*)d_in[2];
    const float* W_rela = (const float*)d_in[3];
    const float* b_rela = (const float*)d_in[4];
    const float* W_att  = (const float*)d_in[5];
    const float* b_att  = (const float*)d_in[6];
    float* out = (float*)d_out;

    prep_kernel<<<128, 512>>>(h, W_att);
    social_kernel<<<PDIM / TI, NTH>>>(h, corr, nei, W_rela, b_rela, W_att, b_att, out);
}